// round 11
// baseline (speedup 1.0000x reference)
#include <cuda_runtime.h>
#include <cooperative_groups.h>
#include <cstdint>
#include <cstddef>

namespace cg = cooperative_groups;

#define BB 64
#define GG 640
#define GH 320
#define DD 256
#define HH 8
#define DHH 32
#define NEGINF (-1e9f)

// ---------------- scratch (static __device__, no allocs) ----------------
__device__ float g_gkey[(size_t)BB * HH * DHH * GG];  // [B][H][dh][G]
__device__ float g_gval[(size_t)BB * HH * DHH * GG];  // [B][H][dh][G]
__device__ float g_lk  [(size_t)BB * DD * GG];        // [B][D][G]
__device__ float g_gemb [BB * DD];
__device__ float g_fixed[BB * DD];

// ---------------- kernel 1: graph mean + fixed context ----------------
__global__ void mean_fixed_kernel(const float* __restrict__ emb,
                                  const float* __restrict__ Wfixed) {
    int b = blockIdx.x;
    int tid = threadIdx.x;  // 256 threads
    __shared__ float ge[DD];
    const float* e = emb + (size_t)b * GG * DD;
    float a0 = 0.f, a1 = 0.f, a2 = 0.f, a3 = 0.f;
    #pragma unroll 4
    for (int g = 0; g < GG; g += 4) {
        a0 += e[(size_t)(g + 0) * DD + tid];
        a1 += e[(size_t)(g + 1) * DD + tid];
        a2 += e[(size_t)(g + 2) * DD + tid];
        a3 += e[(size_t)(g + 3) * DD + tid];
    }
    float m = ((a0 + a1) + (a2 + a3)) * (1.0f / (float)GG);
    ge[tid] = m;
    g_gemb[b * DD + tid] = m;
    __syncthreads();
    float f0 = 0.f, f1 = 0.f, f2 = 0.f, f3 = 0.f;
    #pragma unroll 8
    for (int i = 0; i < DD; i += 4) {
        f0 = fmaf(ge[i + 0], Wfixed[(i + 0) * DD + tid], f0);
        f1 = fmaf(ge[i + 1], Wfixed[(i + 1) * DD + tid], f1);
        f2 = fmaf(ge[i + 2], Wfixed[(i + 2) * DD + tid], f2);
        f3 = fmaf(ge[i + 3], Wfixed[(i + 3) * DD + tid], f3);
    }
    g_fixed[b * DD + tid] = (f0 + f1) + (f2 + f3);
}

// ---------------- kernel 2: kvl GEMM  [40960,256]x[256,768] with scatter epilogue
__global__ void __launch_bounds__(256) kvl_gemm(const float* __restrict__ A,
                                                const float* __restrict__ W) {
    __shared__ float As[32][65];
    __shared__ float Bs[32][68];
    const int bn = blockIdx.x * 64;
    const int bm = blockIdx.y * 64;
    const int tid = threadIdx.x;
    const int tx = tid & 15, ty = tid >> 4;

    float acc[4][4];
    #pragma unroll
    for (int i = 0; i < 4; ++i)
        #pragma unroll
        for (int j = 0; j < 4; ++j) acc[i][j] = 0.f;

    for (int k0 = 0; k0 < DD; k0 += 32) {
        #pragma unroll
        for (int l = 0; l < 2; ++l) {
            int idx = tid * 2 + l;
            int r = idx >> 3, c4 = idx & 7;
            float4 v = *(const float4*)(A + (size_t)(bm + r) * DD + k0 + c4 * 4);
            As[c4 * 4 + 0][r] = v.x;
            As[c4 * 4 + 1][r] = v.y;
            As[c4 * 4 + 2][r] = v.z;
            As[c4 * 4 + 3][r] = v.w;
        }
        #pragma unroll
        for (int l = 0; l < 2; ++l) {
            int idx = tid * 2 + l;
            int r = idx >> 4, c4 = idx & 15;
            float4 v = *(const float4*)(W + (size_t)(k0 + r) * 768 + bn + c4 * 4);
            *(float4*)&Bs[r][c4 * 4] = v;
        }
        __syncthreads();
        #pragma unroll
        for (int k = 0; k < 32; ++k) {
            float a[4], bb[4];
            #pragma unroll
            for (int i = 0; i < 4; ++i) a[i] = As[k][ty * 4 + i];
            #pragma unroll
            for (int j = 0; j < 4; ++j) bb[j] = Bs[k][tx * 4 + j];
            #pragma unroll
            for (int i = 0; i < 4; ++i)
                #pragma unroll
                for (int j = 0; j < 4; ++j) acc[i][j] = fmaf(a[i], bb[j], acc[i][j]);
        }
        __syncthreads();
    }
    #pragma unroll
    for (int i = 0; i < 4; ++i) {
        int m = bm + ty * 4 + i;
        int b = m / GG, g = m % GG;
        #pragma unroll
        for (int j = 0; j < 4; ++j) {
            int n = bn + tx * 4 + j;
            float v = acc[i][j];
            if (n < 256) {
                int h = n >> 5, d = n & 31;
                g_gkey[(((size_t)b * HH + h) * DHH + d) * GG + g] = v;
            } else if (n < 512) {
                int j2 = n - 256;
                int h = j2 >> 5, d = j2 & 31;
                g_gval[(((size_t)b * HH + h) * DHH + d) * GG + g] = v;
            } else {
                int d2 = n - 512;
                g_lk[((size_t)b * DD + d2) * GG + g] = v;
            }
        }
    }
}

// ---------------- kernel 3: 512-step decode, cluster of 2 CTAs per batch row
// Swap-compacted columns: unvisited occupy physical positions [0, n) per rank.
__global__ void __launch_bounds__(640, 1) __cluster_dims__(2, 1, 1)
decode_kernel(const float* __restrict__ emb, const float* __restrict__ Wstep,
              const float* __restrict__ Wout, const int* __restrict__ n_steps_p,
              float* __restrict__ out, int has_pi) {

    cg::cluster_group cl = cg::this_cluster();
    const int rank = (int)(blockIdx.x & 1);
    const int b = blockIdx.x >> 1;
    const int goff = rank * GH;
    const int tid = threadIdx.x;            // 640 threads = 20 warps
    const int warp = tid >> 5, lane = tid & 31;
    const int T = n_steps_p[0];

    __shared__ float fixed_s[DD], prev_s[DD], q_s[DD], heads_s[DD], glimpse_s[DD];
    __shared__ float w_s[HH][GH];           // compat->exp weights; reused as logit partials
    __shared__ float qpart8[8][DD];         // split-K projection partials
    __shared__ float logits_s[GH];
    __shared__ float rmax_s[HH];            // LOCAL row max
    __shared__ float red_s[20];
    __shared__ int   red_i[20];
    __shared__ float mloc_s, lse_s;
    __shared__ int   sel_s;
    __shared__ int   perm_s[GH];            // perm[pos] = global g
    __shared__ int   posOf_s[GH];           // posOf[g - goff] = pos
    __shared__ int   n_s;                   // live (unvisited) count in my half
    __shared__ int   swp_p, swp_l, swp_do;
    // ---- DSMEM exchange buffers (peer reads these) ----
    __shared__ float exc_q[DD];
    __shared__ float exc_heads[DD];
    __shared__ float exc_gl[DD];
    __shared__ float exc_max[HH];
    __shared__ float exc_sum[HH];
    __shared__ float exc_amv;
    __shared__ int   exc_ami;
    __shared__ float exc_ls;

    const int peer = rank ^ 1;
    const float* p_q     = (const float*)cl.map_shared_rank((void*)exc_q, peer);
    const float* p_heads = (const float*)cl.map_shared_rank((void*)exc_heads, peer);
    const float* p_gl    = (const float*)cl.map_shared_rank((void*)exc_gl, peer);
    const float* p_max   = (const float*)cl.map_shared_rank((void*)exc_max, peer);
    const float* p_sum   = (const float*)cl.map_shared_rank((void*)exc_sum, peer);
    const float* p_amv   = (const float*)cl.map_shared_rank((void*)&exc_amv, peer);
    const int*   p_ami   = (const int*)cl.map_shared_rank((void*)&exc_ami, peer);
    const float* p_ls    = (const float*)cl.map_shared_rank((void*)&exc_ls, peer);

    if (tid < DD) {
        fixed_s[tid] = g_fixed[b * DD + tid];
        prev_s[tid]  = g_gemb[b * DD + tid];
    }
    if (tid < GH) { perm_s[tid] = goff + tid; posOf_s[tid] = tid; }
    if (tid == 0) n_s = GH;
    __syncthreads();

    float* gk_b  = g_gkey + (size_t)b * HH * DHH * GG + goff;   // mutable: swaps
    float* gv_b  = g_gval + (size_t)b * HH * DHH * GG + goff;
    float* lk_b  = g_lk   + (size_t)b * DD * GG + goff;
    const float* emb_b = emb + (size_t)b * GG * DD;
    const float inv_sqrt_dh = 0.17677669529663687f;   // 1/sqrt(32)
    const float inv_sqrt_D  = 0.0625f;                // 1/sqrt(256)

    const int pj_p  = tid >> 6;          // 0..9 (used when tid<512)
    const int pj_cq = (tid & 63) * 4;

    for (int t = 0; t < T; ++t) {
        const int n  = n_s;              // live columns in my half
        const int Q  = (n + 3) >> 2;     // live float4 quads
        const int Q4 = Q * 4;
        const int Qe = (Q > 0) ? Q : 1;
        const int mh = tid / Qe;         // head (compat) / d-group (logits)
        const int mq = tid - mh * Qe;
        const int mp4 = mq * 4;          // position quad base
        const bool mvalid = (tid < 8 * Q);

        // ======== q = fixed + prev @ Wstep : split-K across cluster ========
        if (tid < 512) {
            const int kbase = rank * 128 + pj_p * 16;
            const float* wp = Wstep + (size_t)kbase * DD + pj_cq;
            const float* pv = prev_s + kbase;
            float4 a0 = make_float4(0.f, 0.f, 0.f, 0.f);
            float4 a1 = make_float4(0.f, 0.f, 0.f, 0.f);
            #pragma unroll
            for (int i = 0; i < 16; i += 2) {
                float v0 = pv[i], v1 = pv[i + 1];
                float4 w0 = *(const float4*)(wp + (size_t)i * DD);
                float4 w1 = *(const float4*)(wp + (size_t)(i + 1) * DD);
                a0.x = fmaf(v0, w0.x, a0.x); a0.y = fmaf(v0, w0.y, a0.y);
                a0.z = fmaf(v0, w0.z, a0.z); a0.w = fmaf(v0, w0.w, a0.w);
                a1.x = fmaf(v1, w1.x, a1.x); a1.y = fmaf(v1, w1.y, a1.y);
                a1.z = fmaf(v1, w1.z, a1.z); a1.w = fmaf(v1, w1.w, a1.w);
            }
            float4 r;
            r.x = a0.x + a1.x; r.y = a0.y + a1.y; r.z = a0.z + a1.z; r.w = a0.w + a1.w;
            *(float4*)&qpart8[pj_p][pj_cq] = r;
        }
        __syncthreads();
        if (tid < DD) {
            float s = 0.f;
            #pragma unroll
            for (int p = 0; p < 8; ++p) s += qpart8[p][tid];
            exc_q[tid] = s;
        }
        cl.sync();                                   // S1
        if (tid < DD) {
            float lo = rank == 0 ? exc_q[tid] : p_q[tid];
            float hi = rank == 0 ? p_q[tid] : exc_q[tid];
            q_s[tid] = fixed_s[tid] + lo + hi;       // rank-independent order
        }
        __syncthreads();

        // ======== compat over my n live columns, all 8 heads ========
        if (mvalid) {
            const float* base = gk_b + (size_t)mh * DHH * GG + mp4;
            const float* qh = q_s + mh * DHH;
            float ax = 0.f, ay = 0.f, az = 0.f, aw = 0.f;
            #pragma unroll
            for (int d = 0; d < DHH; ++d) {
                float4 kk = *(const float4*)(base + (size_t)d * GG);
                float qd = qh[d];
                ax = fmaf(qd, kk.x, ax);
                ay = fmaf(qd, kk.y, ay);
                az = fmaf(qd, kk.z, az);
                aw = fmaf(qd, kk.w, aw);
            }
            float4 r;
            r.x = (mp4 + 0 < n) ? ax * inv_sqrt_dh : NEGINF;
            r.y = (mp4 + 1 < n) ? ay * inv_sqrt_dh : NEGINF;
            r.z = (mp4 + 2 < n) ? az * inv_sqrt_dh : NEGINF;
            r.w = (mp4 + 3 < n) ? aw * inv_sqrt_dh : NEGINF;
            *(float4*)&w_s[mh][mp4] = r;
        }
        __syncthreads();

        // ======== LOCAL row max over live positions ========
        if (warp < 16) {
            const int h = warp >> 1, half = warp & 1;
            float m = -3e38f;
            #pragma unroll
            for (int k = 0; k < 5; ++k) {
                int p = half * 32 + lane + k * 64;
                if (p < Q4) m = fmaxf(m, w_s[h][p]);
            }
            #pragma unroll
            for (int o = 16; o; o >>= 1) m = fmaxf(m, __shfl_xor_sync(0xffffffffu, m, o));
            if (lane == 0) red_s[warp] = m;
        }
        __syncthreads();
        if (tid < HH) {
            float m = fmaxf(red_s[tid * 2], red_s[tid * 2 + 1]);
            rmax_s[tid] = m;
            exc_max[tid] = m;
        }
        __syncthreads();

        // ======== exp(x - LOCAL max) + local sums (tails -> exactly 0) ========
        if (warp < 16) {
            const int h = warp >> 1, half = warp & 1;
            const float rm = rmax_s[h];
            float s = 0.f;
            #pragma unroll
            for (int k = 0; k < 5; ++k) {
                int p = half * 32 + lane + k * 64;
                if (p < Q4) {
                    float e = expf(w_s[h][p] - rm);
                    w_s[h][p] = e;
                    s += e;
                }
            }
            #pragma unroll
            for (int o = 16; o; o >>= 1) s += __shfl_xor_sync(0xffffffffu, s, o);
            if (lane == 0) red_s[warp] = s;
        }
        __syncthreads();
        if (tid < HH) exc_sum[tid] = red_s[tid * 2] + red_s[tid * 2 + 1];

        // ======== heads partials over live quads (gval STREAMED via ld.cs) ====
        if (warp < 16) {
            #pragma unroll 2
            for (int r = 0; r < 16; ++r) {
                const int row = warp * 16 + r;        // row = h*32 + d
                const int h = row >> 5;
                const float* vrow = gv_b + (size_t)row * GG;
                const float* wrow = &w_s[h][0];
                float ax = 0.f, ay = 0.f, az = 0.f, aw = 0.f;
                #pragma unroll
                for (int c = 0; c < 3; ++c) {
                    int u = lane + c * 32;            // float4 unit
                    if (u < Q) {
                        float4 vv = __ldcs((const float4*)(vrow + u * 4));
                        float4 ww = *(const float4*)(wrow + u * 4);
                        ax = fmaf(ww.x, vv.x, ax);
                        ay = fmaf(ww.y, vv.y, ay);
                        az = fmaf(ww.z, vv.z, az);
                        aw = fmaf(ww.w, vv.w, aw);
                    }
                }
                float s = (ax + ay) + (az + aw);
                #pragma unroll
                for (int o = 16; o; o >>= 1) s += __shfl_xor_sync(0xffffffffu, s, o);
                if (lane == 0) exc_heads[row] = s;
            }
        }
        cl.sync();                                   // S2 (max + sums + head partials)
        if (tid < DD) {
            const int h = tid >> 5;
            float m_lo = rank == 0 ? exc_max[h] : p_max[h];
            float m_hi = rank == 0 ? p_max[h] : exc_max[h];
            float Mg = fmaxf(m_lo, m_hi);
            float e_lo = expf(m_lo - Mg), e_hi = expf(m_hi - Mg);
            float h_lo = rank == 0 ? exc_heads[tid] : p_heads[tid];
            float h_hi = rank == 0 ? p_heads[tid] : exc_heads[tid];
            float s_lo = rank == 0 ? exc_sum[h] : p_sum[h];
            float s_hi = rank == 0 ? p_sum[h] : exc_sum[h];
            heads_s[tid] = (h_lo * e_lo + h_hi * e_hi) / (s_lo * e_lo + s_hi * e_hi);
        }
        __syncthreads();

        // ======== glimpse = heads @ Wout : split-K across cluster ========
        if (tid < 512) {
            const int kbase = rank * 128 + pj_p * 16;
            const float* wp = Wout + (size_t)kbase * DD + pj_cq;
            const float* hv = heads_s + kbase;
            float4 a0 = make_float4(0.f, 0.f, 0.f, 0.f);
            float4 a1 = make_float4(0.f, 0.f, 0.f, 0.f);
            #pragma unroll
            for (int i = 0; i < 16; i += 2) {
                float v0 = hv[i], v1 = hv[i + 1];
                float4 w0 = *(const float4*)(wp + (size_t)i * DD);
                float4 w1 = *(const float4*)(wp + (size_t)(i + 1) * DD);
                a0.x = fmaf(v0, w0.x, a0.x); a0.y = fmaf(v0, w0.y, a0.y);
                a0.z = fmaf(v0, w0.z, a0.z); a0.w = fmaf(v0, w0.w, a0.w);
                a1.x = fmaf(v1, w1.x, a1.x); a1.y = fmaf(v1, w1.y, a1.y);
                a1.z = fmaf(v1, w1.z, a1.z); a1.w = fmaf(v1, w1.w, a1.w);
            }
            float4 r;
            r.x = a0.x + a1.x; r.y = a0.y + a1.y; r.z = a0.z + a1.z; r.w = a0.w + a1.w;
            *(float4*)&qpart8[pj_p][pj_cq] = r;
        }
        __syncthreads();
        if (tid < DD) {
            float s = 0.f;
            #pragma unroll
            for (int p = 0; p < 8; ++p) s += qpart8[p][tid];
            exc_gl[tid] = s;
        }
        cl.sync();                                   // S3
        if (tid < DD) {
            float lo = rank == 0 ? exc_gl[tid] : p_gl[tid];
            float hi = rank == 0 ? p_gl[tid] : exc_gl[tid];
            glimpse_s[tid] = lo + hi;
        }
        __syncthreads();

        // ======== logits partials: 8 d-groups x live quads (into w_s) ========
        if (mvalid) {
            const float* base = lk_b + (size_t)(mh * 32) * GG + mp4;
            const float* gl = glimpse_s + mh * 32;
            float ax = 0.f, ay = 0.f, az = 0.f, aw = 0.f;
            #pragma unroll 8
            for (int d = 0; d < 32; ++d) {
                float4 kk = *(const float4*)(base + (size_t)d * GG);
                float gv2 = gl[d];
                ax = fmaf(gv2, kk.x, ax);
                ay = fmaf(gv2, kk.y, ay);
                az = fmaf(gv2, kk.z, az);
                aw = fmaf(gv2, kk.w, aw);
            }
            float4 r; r.x = ax; r.y = ay; r.z = az; r.w = aw;
            *(float4*)&w_s[mh][mp4] = r;
        }
        __syncthreads();
        if (tid < Q4) {
            float l = ((w_s[0][tid] + w_s[1][tid]) + (w_s[2][tid] + w_s[3][tid]))
                    + ((w_s[4][tid] + w_s[5][tid]) + (w_s[6][tid] + w_s[7][tid]));
            l = 10.0f * tanhf(l * inv_sqrt_D);
            logits_s[tid] = l;                       // only [0,n) ever consumed
        }
        __syncthreads();

        // ======== local argmax over live positions (carry global g) ========
        if (tid < GH) {
            bool live = tid < n;
            float v = live ? logits_s[tid] : -3e38f;
            int idx = live ? perm_s[tid] : 0x7fffffff;
            #pragma unroll
            for (int o = 16; o; o >>= 1) {
                float ov = __shfl_xor_sync(0xffffffffu, v, o);
                int oi = __shfl_xor_sync(0xffffffffu, idx, o);
                if (ov > v || (ov == v && oi < idx)) { v = ov; idx = oi; }
            }
            if (lane == 0) { red_s[warp] = v; red_i[warp] = idx; }
        }
        __syncthreads();
        if (tid == 0) {
            float v = red_s[0]; int idx = red_i[0];
            #pragma unroll
            for (int wv = 1; wv < 10; ++wv) {
                if (red_s[wv] > v || (red_s[wv] == v && red_i[wv] < idx)) {
                    v = red_s[wv]; idx = red_i[wv];
                }
            }
            exc_amv = v; exc_ami = idx; mloc_s = v;   // local max
        }
        __syncthreads();
        const float mloc = mloc_s;
        // local sumexp at LOCAL max
        if (tid < GH) {
            float e = (tid < n) ? expf(logits_s[tid] - mloc) : 0.f;
            #pragma unroll
            for (int o = 16; o; o >>= 1) e += __shfl_xor_sync(0xffffffffu, e, o);
            if (lane == 0) red_s[warp] = e;
        }
        __syncthreads();
        if (tid == 0) {
            float s = 0.f;
            #pragma unroll
            for (int wv = 0; wv < 10; ++wv) s += red_s[wv];
            exc_ls = s;
        }
        cl.sync();                                   // S4 (argmax + lse merged)
        if (tid == 0) {
            float m0 = rank == 0 ? exc_amv : *p_amv;
            int   i0 = rank == 0 ? exc_ami : *p_ami;
            float s0 = rank == 0 ? exc_ls  : *p_ls;
            float m1 = rank == 0 ? *p_amv : exc_amv;
            int   i1 = rank == 0 ? *p_ami : exc_ami;
            float s1 = rank == 0 ? *p_ls  : exc_ls;
            int sel = (m1 > m0 || (m1 == m0 && i1 < i0)) ? i1 : i0;
            float Mg = fmaxf(m0, m1);
            float lse = Mg + logf(s0 * expf(m0 - Mg) + s1 * expf(m1 - Mg));
            sel_s = sel; lse_s = lse;
        }
        __syncthreads();
        const float lse = lse_s;
        const int sel = sel_s;

        // ======== outputs (streaming stores; visited -> exactly NEGINF - lse) ====
        if (tid < GH) {
            int pos = posOf_s[tid];
            float val = (pos < n) ? (logits_s[pos] - lse) : (NEGINF - lse);
            __stcs(&out[((size_t)b * T + t) * GG + goff + tid], val);
        }
        if (has_pi && rank == 0 && tid == 0)
            __stcs(&out[(size_t)BB * T * GG + (size_t)b * T + t], (float)sel);

        // ======== state update: prev embed + compaction bookkeeping ========
        if (tid < DD) prev_s[tid] = __ldcs(&emb_b[(size_t)sel * DD + tid]);
        __syncthreads();                              // outputs done before swap
        if (tid == 0) {
            swp_do = 0;
            if (sel >= goff && sel < goff + GH) {
                int lg = sel - goff;
                int p = posOf_s[lg];
                int last = n - 1;
                int glast = perm_s[last];
                perm_s[p] = glast; perm_s[last] = sel;
                posOf_s[glast - goff] = p; posOf_s[lg] = last;
                n_s = last;
                if (p != last) { swp_p = p; swp_l = last; swp_do = 1; }
            }
        }
        __syncthreads();
        if (swp_do) {                                 // swap columns p<->l in 3 arrays
            const int p = swp_p, l = swp_l;
            for (int i = tid; i < 3 * 256; i += 640) {
                float* arr = (i < 256) ? gk_b : (i < 512) ? gv_b : lk_b;
                float* row = arr + (size_t)(i & 255) * GG;
                float tmp = row[p]; row[p] = row[l]; row[l] = tmp;
            }
        }
        __syncthreads();
    }
}

// ---------------- launch ----------------
extern "C" void kernel_launch(void* const* d_in, const int* in_sizes, int n_in,
                              void* d_out, int out_size) {
    const float* emb    = (const float*)d_in[0];
    const float* Wnode  = (const float*)d_in[1];
    const float* Wfixed = (const float*)d_in[2];
    const float* Wstep  = (const float*)d_in[3];
    const float* Wout   = (const float*)d_in[4];
    const int*   nsteps = (const int*)d_in[5];
    float* out = (float*)d_out;

    int has_pi = (out_size % (BB * (GG + 1)) == 0) ? 1 : 0;

    mean_fixed_kernel<<<BB, DD>>>(emb, Wfixed);

    dim3 ggrid(12, 640);      // 768/64 x 40960/64
    kvl_gemm<<<ggrid, 256>>>(emb, Wnode);

    decode_kernel<<<BB * 2, GG>>>(emb, Wstep, Wout, nsteps, out, has_pi);
}

// round 12
// speedup vs baseline: 1.1931x; 1.1931x over previous
#include <cuda_runtime.h>
#include <cooperative_groups.h>
#include <cstdint>
#include <cstddef>

namespace cg = cooperative_groups;

#define BB 64
#define GG 640
#define GH 320
#define DD 256
#define HH 8
#define DHH 32
#define NEGINF (-1e9f)

// dynamic smem: Wstep half (128x256) + Wout first 64 rows of half (64x256)
#define WS_FLOATS (128 * 256)
#define WO_FLOATS (64 * 256)
#define DYN_BYTES ((WS_FLOATS + WO_FLOATS) * 4)

// ---------------- scratch (static __device__, no allocs) ----------------
__device__ float g_gkey[(size_t)BB * HH * DHH * GG];  // [B][H][dh][G]
__device__ float g_gval[(size_t)BB * HH * DHH * GG];  // [B][H][dh][G]
__device__ float g_lk  [(size_t)BB * DD * GG];        // [B][D][G]
__device__ float g_gemb [BB * DD];
__device__ float g_fixed[BB * DD];

// ---------------- kernel 1: graph mean + fixed context ----------------
__global__ void mean_fixed_kernel(const float* __restrict__ emb,
                                  const float* __restrict__ Wfixed) {
    int b = blockIdx.x;
    int tid = threadIdx.x;  // 256 threads
    __shared__ float ge[DD];
    const float* e = emb + (size_t)b * GG * DD;
    float a0 = 0.f, a1 = 0.f, a2 = 0.f, a3 = 0.f;
    #pragma unroll 4
    for (int g = 0; g < GG; g += 4) {
        a0 += e[(size_t)(g + 0) * DD + tid];
        a1 += e[(size_t)(g + 1) * DD + tid];
        a2 += e[(size_t)(g + 2) * DD + tid];
        a3 += e[(size_t)(g + 3) * DD + tid];
    }
    float m = ((a0 + a1) + (a2 + a3)) * (1.0f / (float)GG);
    ge[tid] = m;
    g_gemb[b * DD + tid] = m;
    __syncthreads();
    float f0 = 0.f, f1 = 0.f, f2 = 0.f, f3 = 0.f;
    #pragma unroll 8
    for (int i = 0; i < DD; i += 4) {
        f0 = fmaf(ge[i + 0], Wfixed[(i + 0) * DD + tid], f0);
        f1 = fmaf(ge[i + 1], Wfixed[(i + 1) * DD + tid], f1);
        f2 = fmaf(ge[i + 2], Wfixed[(i + 2) * DD + tid], f2);
        f3 = fmaf(ge[i + 3], Wfixed[(i + 3) * DD + tid], f3);
    }
    g_fixed[b * DD + tid] = (f0 + f1) + (f2 + f3);
}

// ---------------- kernel 2: kvl GEMM  [40960,256]x[256,768] with scatter epilogue
__global__ void __launch_bounds__(256) kvl_gemm(const float* __restrict__ A,
                                                const float* __restrict__ W) {
    __shared__ float As[32][65];
    __shared__ float Bs[32][68];
    const int bn = blockIdx.x * 64;
    const int bm = blockIdx.y * 64;
    const int tid = threadIdx.x;
    const int tx = tid & 15, ty = tid >> 4;

    float acc[4][4];
    #pragma unroll
    for (int i = 0; i < 4; ++i)
        #pragma unroll
        for (int j = 0; j < 4; ++j) acc[i][j] = 0.f;

    for (int k0 = 0; k0 < DD; k0 += 32) {
        #pragma unroll
        for (int l = 0; l < 2; ++l) {
            int idx = tid * 2 + l;
            int r = idx >> 3, c4 = idx & 7;
            float4 v = *(const float4*)(A + (size_t)(bm + r) * DD + k0 + c4 * 4);
            As[c4 * 4 + 0][r] = v.x;
            As[c4 * 4 + 1][r] = v.y;
            As[c4 * 4 + 2][r] = v.z;
            As[c4 * 4 + 3][r] = v.w;
        }
        #pragma unroll
        for (int l = 0; l < 2; ++l) {
            int idx = tid * 2 + l;
            int r = idx >> 4, c4 = idx & 15;
            float4 v = *(const float4*)(W + (size_t)(k0 + r) * 768 + bn + c4 * 4);
            *(float4*)&Bs[r][c4 * 4] = v;
        }
        __syncthreads();
        #pragma unroll
        for (int k = 0; k < 32; ++k) {
            float a[4], bb[4];
            #pragma unroll
            for (int i = 0; i < 4; ++i) a[i] = As[k][ty * 4 + i];
            #pragma unroll
            for (int j = 0; j < 4; ++j) bb[j] = Bs[k][tx * 4 + j];
            #pragma unroll
            for (int i = 0; i < 4; ++i)
                #pragma unroll
                for (int j = 0; j < 4; ++j) acc[i][j] = fmaf(a[i], bb[j], acc[i][j]);
        }
        __syncthreads();
    }
    #pragma unroll
    for (int i = 0; i < 4; ++i) {
        int m = bm + ty * 4 + i;
        int b = m / GG, g = m % GG;
        #pragma unroll
        for (int j = 0; j < 4; ++j) {
            int n = bn + tx * 4 + j;
            float v = acc[i][j];
            if (n < 256) {
                int h = n >> 5, d = n & 31;
                g_gkey[(((size_t)b * HH + h) * DHH + d) * GG + g] = v;
            } else if (n < 512) {
                int j2 = n - 256;
                int h = j2 >> 5, d = j2 & 31;
                g_gval[(((size_t)b * HH + h) * DHH + d) * GG + g] = v;
            } else {
                int d2 = n - 512;
                g_lk[((size_t)b * DD + d2) * GG + g] = v;
            }
        }
    }
}

// ---------------- kernel 3: 512-step decode, cluster of 2 CTAs per batch row
// Weights pinned in SMEM: Wstep K-half fully, Wout K-half rows [0,64).
__global__ void __launch_bounds__(640, 1) __cluster_dims__(2, 1, 1)
decode_kernel(const float* __restrict__ emb, const float* __restrict__ Wstep,
              const float* __restrict__ Wout, const int* __restrict__ n_steps_p,
              float* __restrict__ out, int has_pi) {

    extern __shared__ float dyn_s[];
    float* ws_step = dyn_s;                 // [128][256]
    float* ws_out  = dyn_s + WS_FLOATS;     // [64][256]

    cg::cluster_group cl = cg::this_cluster();
    const int rank = (int)(blockIdx.x & 1);
    const int b = blockIdx.x >> 1;
    const int goff = rank * GH;
    const int tid = threadIdx.x;            // 640 threads = 20 warps
    const int warp = tid >> 5, lane = tid & 31;
    const int T = n_steps_p[0];

    __shared__ float fixed_s[DD], prev_s[DD], q_s[DD], heads_s[DD], glimpse_s[DD];
    __shared__ float w_s[HH][GH];           // compat->exp weights; reused as logit partials
    __shared__ float qpart8[8][DD];         // split-K projection partials
    __shared__ float logits_s[GH];
    __shared__ float rmax_s[HH];            // LOCAL row max
    __shared__ float red_s[20];
    __shared__ int   red_i[20];
    __shared__ float mloc_s, lse_s;
    __shared__ int   sel_s;
    __shared__ unsigned char visited_s[GH];
    // ---- DSMEM exchange buffers (peer reads these) ----
    __shared__ float exc_q[DD];
    __shared__ float exc_heads[DD];
    __shared__ float exc_gl[DD];
    __shared__ float exc_max[HH];
    __shared__ float exc_sum[HH];
    __shared__ float exc_amv;
    __shared__ int   exc_ami;
    __shared__ float exc_ls;

    const int peer = rank ^ 1;
    const float* p_q     = (const float*)cl.map_shared_rank((void*)exc_q, peer);
    const float* p_heads = (const float*)cl.map_shared_rank((void*)exc_heads, peer);
    const float* p_gl    = (const float*)cl.map_shared_rank((void*)exc_gl, peer);
    const float* p_max   = (const float*)cl.map_shared_rank((void*)exc_max, peer);
    const float* p_sum   = (const float*)cl.map_shared_rank((void*)exc_sum, peer);
    const float* p_amv   = (const float*)cl.map_shared_rank((void*)&exc_amv, peer);
    const int*   p_ami   = (const int*)cl.map_shared_rank((void*)&exc_ami, peer);
    const float* p_ls    = (const float*)cl.map_shared_rank((void*)&exc_ls, peer);

    if (tid < DD) {
        fixed_s[tid] = g_fixed[b * DD + tid];
        prev_s[tid]  = g_gemb[b * DD + tid];
    }
    if (tid < GH) visited_s[tid] = 0;

    // ---- preload weights into SMEM (one-time) ----
    {
        const float* src = Wstep + (size_t)(rank * 128) * DD;
        for (int i = tid; i < WS_FLOATS / 4; i += 640) {
            *(float4*)&ws_step[i * 4] = *(const float4*)(src + i * 4);
        }
        const float* src2 = Wout + (size_t)(rank * 128) * DD;
        for (int i = tid; i < WO_FLOATS / 4; i += 640) {
            *(float4*)&ws_out[i * 4] = *(const float4*)(src2 + i * 4);
        }
    }
    __syncthreads();

    const float* gk_b  = g_gkey + (size_t)b * HH * DHH * GG + goff;
    const float* gv_b  = g_gval + (size_t)b * HH * DHH * GG + goff;
    const float* lk_b  = g_lk   + (size_t)b * DD * GG + goff;
    const float* emb_b = emb    + (size_t)b * GG * DD;
    const float inv_sqrt_dh = 0.17677669529663687f;   // 1/sqrt(32)
    const float inv_sqrt_D  = 0.0625f;                // 1/sqrt(256)

    const int cp_h  = tid / 80;          // head (compat) / d-group (logits)
    const int cp_g4 = (tid % 80) * 4;    // local g quad base
    const int pj_p  = tid >> 6;          // 0..9 (used when tid<512)
    const int pj_cq = (tid & 63) * 4;

    for (int t = 0; t < T; ++t) {
        // ======== q = fixed + prev @ Wstep : split-K across cluster (SMEM weights) ====
        if (tid < 512) {
            const float* wp = ws_step + (size_t)(pj_p * 16) * DD + pj_cq;
            const float* pv = prev_s + rank * 128 + pj_p * 16;
            float4 a0 = make_float4(0.f, 0.f, 0.f, 0.f);
            float4 a1 = make_float4(0.f, 0.f, 0.f, 0.f);
            #pragma unroll
            for (int i = 0; i < 16; i += 2) {
                float v0 = pv[i], v1 = pv[i + 1];
                float4 w0 = *(const float4*)(wp + (size_t)i * DD);
                float4 w1 = *(const float4*)(wp + (size_t)(i + 1) * DD);
                a0.x = fmaf(v0, w0.x, a0.x); a0.y = fmaf(v0, w0.y, a0.y);
                a0.z = fmaf(v0, w0.z, a0.z); a0.w = fmaf(v0, w0.w, a0.w);
                a1.x = fmaf(v1, w1.x, a1.x); a1.y = fmaf(v1, w1.y, a1.y);
                a1.z = fmaf(v1, w1.z, a1.z); a1.w = fmaf(v1, w1.w, a1.w);
            }
            float4 r;
            r.x = a0.x + a1.x; r.y = a0.y + a1.y; r.z = a0.z + a1.z; r.w = a0.w + a1.w;
            *(float4*)&qpart8[pj_p][pj_cq] = r;
        }
        __syncthreads();
        if (tid < DD) {
            float s = 0.f;
            #pragma unroll
            for (int p = 0; p < 8; ++p) s += qpart8[p][tid];
            exc_q[tid] = s;
        }
        cl.sync();                                   // S1
        if (tid < DD) {
            float lo = rank == 0 ? exc_q[tid] : p_q[tid];
            float hi = rank == 0 ? p_q[tid] : exc_q[tid];
            q_s[tid] = fixed_s[tid] + lo + hi;       // rank-independent order
        }
        __syncthreads();

        // ======== compat over my 320 g's, all 8 heads ========
        {
            unsigned char v0 = visited_s[cp_g4 + 0], v1 = visited_s[cp_g4 + 1];
            unsigned char v2 = visited_s[cp_g4 + 2], v3 = visited_s[cp_g4 + 3];
            const float* base = gk_b + (size_t)cp_h * DHH * GG + cp_g4;
            const float* qh = q_s + cp_h * DHH;
            float ax = 0.f, ay = 0.f, az = 0.f, aw = 0.f;
            #pragma unroll
            for (int d = 0; d < DHH; ++d) {
                float4 kk = *(const float4*)(base + (size_t)d * GG);
                float qd = qh[d];
                ax = fmaf(qd, kk.x, ax);
                ay = fmaf(qd, kk.y, ay);
                az = fmaf(qd, kk.z, az);
                aw = fmaf(qd, kk.w, aw);
            }
            float4 r;
            r.x = v0 ? NEGINF : ax * inv_sqrt_dh;
            r.y = v1 ? NEGINF : ay * inv_sqrt_dh;
            r.z = v2 ? NEGINF : az * inv_sqrt_dh;
            r.w = v3 ? NEGINF : aw * inv_sqrt_dh;
            *(float4*)&w_s[cp_h][cp_g4] = r;
        }
        __syncthreads();

        // ======== LOCAL row max ========
        if (warp < 16) {
            const int h = warp >> 1, half = warp & 1;
            const float* row = &w_s[h][half * 160];
            float m = -3e38f;
            #pragma unroll
            for (int k = 0; k < 5; ++k) m = fmaxf(m, row[lane + k * 32]);
            #pragma unroll
            for (int o = 16; o; o >>= 1) m = fmaxf(m, __shfl_xor_sync(0xffffffffu, m, o));
            if (lane == 0) red_s[warp] = m;
        }
        __syncthreads();
        if (tid < HH) {
            float m = fmaxf(red_s[tid * 2], red_s[tid * 2 + 1]);
            rmax_s[tid] = m;
            exc_max[tid] = m;
        }
        __syncthreads();

        // ======== exp(x - LOCAL max) + local sums ========
        if (warp < 16) {
            const int h = warp >> 1, half = warp & 1;
            const float rm = rmax_s[h];
            float* row = &w_s[h][half * 160];
            float s = 0.f;
            #pragma unroll
            for (int k = 0; k < 5; ++k) {
                float e = expf(row[lane + k * 32] - rm);
                row[lane + k * 32] = e;
                s += e;
            }
            #pragma unroll
            for (int o = 16; o; o >>= 1) s += __shfl_xor_sync(0xffffffffu, s, o);
            if (lane == 0) red_s[warp] = s;
        }
        __syncthreads();
        if (tid < HH) exc_sum[tid] = red_s[tid * 2] + red_s[tid * 2 + 1];

        // ======== heads partials over my 320 g's (gval STREAMED via ld.cs) ====
        if (warp < 16) {
            #pragma unroll 2
            for (int r = 0; r < 16; ++r) {
                const int row = warp * 16 + r;        // row = h*32 + d
                const int h = row >> 5;
                const float* vrow = gv_b + (size_t)row * GG;
                const float* wrow = &w_s[h][0];
                float ax = 0.f, ay = 0.f, az = 0.f, aw = 0.f;
                #pragma unroll
                for (int c = 0; c < 3; ++c) {
                    int u = lane + c * 32;            // float4 unit, 80 total
                    if (u < 80) {
                        float4 vv = __ldcs((const float4*)(vrow + u * 4));
                        float4 ww = *(const float4*)(wrow + u * 4);
                        ax = fmaf(ww.x, vv.x, ax);
                        ay = fmaf(ww.y, vv.y, ay);
                        az = fmaf(ww.z, vv.z, az);
                        aw = fmaf(ww.w, vv.w, aw);
                    }
                }
                float s = (ax + ay) + (az + aw);
                #pragma unroll
                for (int o = 16; o; o >>= 1) s += __shfl_xor_sync(0xffffffffu, s, o);
                if (lane == 0) exc_heads[row] = s;
            }
        }
        cl.sync();                                   // S2 (max + sums + head partials)
        if (tid < DD) {
            const int h = tid >> 5;
            float m_lo = rank == 0 ? exc_max[h] : p_max[h];
            float m_hi = rank == 0 ? p_max[h] : exc_max[h];
            float Mg = fmaxf(m_lo, m_hi);
            float e_lo = expf(m_lo - Mg), e_hi = expf(m_hi - Mg);
            float h_lo = rank == 0 ? exc_heads[tid] : p_heads[tid];
            float h_hi = rank == 0 ? p_heads[tid] : exc_heads[tid];
            float s_lo = rank == 0 ? exc_sum[h] : p_sum[h];
            float s_hi = rank == 0 ? p_sum[h] : exc_sum[h];
            heads_s[tid] = (h_lo * e_lo + h_hi * e_hi) / (s_lo * e_lo + s_hi * e_hi);
        }
        __syncthreads();

        // ======== glimpse = heads @ Wout : split-K (SMEM rows 0-63, L2 rows 64-127) ====
        if (tid < 512) {
            const float* wp;
            if (pj_p < 4)
                wp = ws_out + (size_t)(pj_p * 16) * DD + pj_cq;
            else
                wp = Wout + (size_t)(rank * 128 + pj_p * 16) * DD + pj_cq;
            const float* hv = heads_s + rank * 128 + pj_p * 16;
            float4 a0 = make_float4(0.f, 0.f, 0.f, 0.f);
            float4 a1 = make_float4(0.f, 0.f, 0.f, 0.f);
            #pragma unroll
            for (int i = 0; i < 16; i += 2) {
                float v0 = hv[i], v1 = hv[i + 1];
                float4 w0 = *(const float4*)(wp + (size_t)i * DD);
                float4 w1 = *(const float4*)(wp + (size_t)(i + 1) * DD);
                a0.x = fmaf(v0, w0.x, a0.x); a0.y = fmaf(v0, w0.y, a0.y);
                a0.z = fmaf(v0, w0.z, a0.z); a0.w = fmaf(v0, w0.w, a0.w);
                a1.x = fmaf(v1, w1.x, a1.x); a1.y = fmaf(v1, w1.y, a1.y);
                a1.z = fmaf(v1, w1.z, a1.z); a1.w = fmaf(v1, w1.w, a1.w);
            }
            float4 r;
            r.x = a0.x + a1.x; r.y = a0.y + a1.y; r.z = a0.z + a1.z; r.w = a0.w + a1.w;
            *(float4*)&qpart8[pj_p][pj_cq] = r;
        }
        __syncthreads();
        if (tid < DD) {
            float s = 0.f;
            #pragma unroll
            for (int p = 0; p < 8; ++p) s += qpart8[p][tid];
            exc_gl[tid] = s;
        }
        cl.sync();                                   // S3
        if (tid < DD) {
            float lo = rank == 0 ? exc_gl[tid] : p_gl[tid];
            float hi = rank == 0 ? p_gl[tid] : exc_gl[tid];
            glimpse_s[tid] = lo + hi;
        }
        __syncthreads();

        // ======== logits partials: 8 d-groups x 80 g-quads (into w_s) ========
        {
            const float* base = lk_b + (size_t)(cp_h * 32) * GG + cp_g4;
            const float* gl = glimpse_s + cp_h * 32;
            float ax = 0.f, ay = 0.f, az = 0.f, aw = 0.f;
            #pragma unroll 8
            for (int d = 0; d < 32; ++d) {
                float4 kk = *(const float4*)(base + (size_t)d * GG);
                float gv2 = gl[d];
                ax = fmaf(gv2, kk.x, ax);
                ay = fmaf(gv2, kk.y, ay);
                az = fmaf(gv2, kk.z, az);
                aw = fmaf(gv2, kk.w, aw);
            }
            float4 r; r.x = ax; r.y = ay; r.z = az; r.w = aw;
            *(float4*)&w_s[cp_h][cp_g4] = r;
        }
        __syncthreads();
        if (tid < GH) {
            float l = ((w_s[0][tid] + w_s[1][tid]) + (w_s[2][tid] + w_s[3][tid]))
                    + ((w_s[4][tid] + w_s[5][tid]) + (w_s[6][tid] + w_s[7][tid]));
            l = 10.0f * tanhf(l * inv_sqrt_D);
            logits_s[tid] = visited_s[tid] ? NEGINF : l;
        }
        __syncthreads();

        // ======== local argmax over my 320 (first occurrence, global idx) ====
        if (tid < GH) {
            float v = logits_s[tid];
            int idx = goff + tid;
            #pragma unroll
            for (int o = 16; o; o >>= 1) {
                float ov = __shfl_xor_sync(0xffffffffu, v, o);
                int oi = __shfl_xor_sync(0xffffffffu, idx, o);
                if (ov > v || (ov == v && oi < idx)) { v = ov; idx = oi; }
            }
            if (lane == 0) { red_s[warp] = v; red_i[warp] = idx; }
        }
        __syncthreads();
        if (tid == 0) {
            float v = red_s[0]; int idx = red_i[0];
            #pragma unroll
            for (int wv = 1; wv < 10; ++wv) {
                if (red_s[wv] > v || (red_s[wv] == v && red_i[wv] < idx)) {
                    v = red_s[wv]; idx = red_i[wv];
                }
            }
            exc_amv = v; exc_ami = idx; mloc_s = v;   // local max
        }
        __syncthreads();
        const float mloc = mloc_s;
        // local sumexp at LOCAL max
        if (tid < GH) {
            float e = expf(logits_s[tid] - mloc);
            #pragma unroll
            for (int o = 16; o; o >>= 1) e += __shfl_xor_sync(0xffffffffu, e, o);
            if (lane == 0) red_s[warp] = e;
        }
        __syncthreads();
        if (tid == 0) {
            float s = 0.f;
            #pragma unroll
            for (int wv = 0; wv < 10; ++wv) s += red_s[wv];
            exc_ls = s;
        }
        cl.sync();                                   // S4 (argmax + lse merged)
        if (tid == 0) {
            float m0 = rank == 0 ? exc_amv : *p_amv;
            int   i0 = rank == 0 ? exc_ami : *p_ami;
            float s0 = rank == 0 ? exc_ls  : *p_ls;
            float m1 = rank == 0 ? *p_amv : exc_amv;
            int   i1 = rank == 0 ? *p_ami : exc_ami;
            float s1 = rank == 0 ? *p_ls  : exc_ls;
            int sel = (m1 > m0 || (m1 == m0 && i1 < i0)) ? i1 : i0;
            float Mg = fmaxf(m0, m1);
            float lse = Mg + logf(s0 * expf(m0 - Mg) + s1 * expf(m1 - Mg));
            sel_s = sel; lse_s = lse;
        }
        __syncthreads();
        const float lse = lse_s;
        const int sel = sel_s;

        // ======== outputs (streaming stores) ========
        if (tid < GH)
            __stcs(&out[((size_t)b * T + t) * GG + goff + tid], logits_s[tid] - lse);
        if (has_pi && rank == 0 && tid == 0)
            __stcs(&out[(size_t)BB * T * GG + (size_t)b * T + t], (float)sel);

        // ======== state update ========
        if (tid == 0 && (sel >> 5) / 10 == rank)     // sel/320 == rank
            visited_s[sel - goff] = 1;
        if (tid < DD) prev_s[tid] = __ldcs(&emb_b[(size_t)sel * DD + tid]);
        __syncthreads();
    }
}

// ---------------- launch ----------------
extern "C" void kernel_launch(void* const* d_in, const int* in_sizes, int n_in,
                              void* d_out, int out_size) {
    const float* emb    = (const float*)d_in[0];
    const float* Wnode  = (const float*)d_in[1];
    const float* Wfixed = (const float*)d_in[2];
    const float* Wstep  = (const float*)d_in[3];
    const float* Wout   = (const float*)d_in[4];
    const int*   nsteps = (const int*)d_in[5];
    float* out = (float*)d_out;

    int has_pi = (out_size % (BB * (GG + 1)) == 0) ? 1 : 0;

    cudaFuncSetAttribute(decode_kernel,
                         cudaFuncAttributeMaxDynamicSharedMemorySize, DYN_BYTES);

    mean_fixed_kernel<<<BB, DD>>>(emb, Wfixed);

    dim3 ggrid(12, 640);      // 768/64 x 40960/64
    kvl_gemm<<<ggrid, 256>>>(emb, Wnode);

    decode_kernel<<<BB * 2, GG, DYN_BYTES>>>(emb, Wstep, Wout, nsteps, out, has_pi);
}